// round 9
// baseline (speedup 1.0000x reference)
#include <cuda_runtime.h>

// Problem constants (fixed-shape problem)
#define WIN   48
#define DIN   64
#define DOUT  128
#define BATCH 4096
#define NSEG  (BATCH * WIN)      // 196608 segments
#define NEV_MAX 2000000
#define SCAN_BLK 2048            // elems per scan block
#define SCAN_NBLK (NSEG / SCAN_BLK)   // 96

// Scratch
__device__ int   g_cnt[NSEG];            // events per segment
__device__ int   g_cur[NSEG];            // exclusive offsets (then cursors -> end)
__device__ int   g_part[SCAN_NBLK];      // scan partials (block totals)
__device__ int   g_bucket[NEV_MAX];      // event ids grouped by segment
__device__ float g_mean[NSEG * DIN];     // segment means (written, never atomically)

// ---------------------------------------------------------------------------
// 1) zero counters
// ---------------------------------------------------------------------------
__global__ void zero_cnt_kernel() {
    int i = blockIdx.x * blockDim.x + threadIdx.x;
    if (i < NSEG) g_cnt[i] = 0;
}

// ---------------------------------------------------------------------------
// 2) histogram: events per segment
// ---------------------------------------------------------------------------
__global__ void hist_kernel(const int* __restrict__ bi,
                            const int* __restrict__ wi, int n) {
    int i = blockIdx.x * blockDim.x + threadIdx.x;
    if (i >= n) return;
    int seg = bi[i] * WIN + wi[i];
    atomicAdd(&g_cnt[seg], 1);
}

// ---------------------------------------------------------------------------
// 3a) per-2048-block exclusive scan; block totals -> g_part
// ---------------------------------------------------------------------------
__global__ __launch_bounds__(1024) void scan_a_kernel() {
    __shared__ int warp_tot[32];
    int tid = threadIdx.x;
    int base = blockIdx.x * SCAN_BLK;
    int a = g_cnt[base + 2 * tid];
    int b = g_cnt[base + 2 * tid + 1];
    int s = a + b;
    int lane = tid & 31, wid = tid >> 5;
    int v = s;
    #pragma unroll
    for (int o = 1; o < 32; o <<= 1) {
        int t = __shfl_up_sync(0xffffffffu, v, o);
        if (lane >= o) v += t;
    }
    if (lane == 31) warp_tot[wid] = v;
    __syncthreads();
    if (wid == 0) {
        int w = warp_tot[lane];
        #pragma unroll
        for (int o = 1; o < 32; o <<= 1) {
            int t = __shfl_up_sync(0xffffffffu, w, o);
            if (lane >= o) w += t;
        }
        warp_tot[lane] = w;   // inclusive warp totals
    }
    __syncthreads();
    int warp_off = (wid == 0) ? 0 : warp_tot[wid - 1];
    int incl = v + warp_off;              // inclusive over block (this pair)
    g_cur[base + 2 * tid]     = incl - s; // exclusive for a
    g_cur[base + 2 * tid + 1] = incl - b; // exclusive for b
    if (tid == 1023) g_part[blockIdx.x] = incl;
}

// ---------------------------------------------------------------------------
// 3b) add global prefix: each 256-block computes sum of g_part[0..sb) itself
// ---------------------------------------------------------------------------
__global__ __launch_bounds__(256) void scan_c_kernel() {
    __shared__ int s_off;
    int blk = blockIdx.x;
    int sb = blk >> 3;                // which 2048-scan-block we belong to
    if (threadIdx.x < 32) {
        int acc = 0;
        for (int i = threadIdx.x; i < sb; i += 32) acc += g_part[i];
        #pragma unroll
        for (int o = 16; o > 0; o >>= 1)
            acc += __shfl_down_sync(0xffffffffu, acc, o);
        if (threadIdx.x == 0) s_off = acc;
    }
    __syncthreads();
    g_cur[blk * 256 + threadIdx.x] += s_off;
}

// ---------------------------------------------------------------------------
// 4) scatter event indices into buckets (g_cur becomes END offset)
// ---------------------------------------------------------------------------
__global__ void scatter_idx_kernel(const int* __restrict__ bi,
                                   const int* __restrict__ wi, int n) {
    int i = blockIdx.x * blockDim.x + threadIdx.x;
    if (i >= n) return;
    int seg = bi[i] * WIN + wi[i];
    int pos = atomicAdd(&g_cur[seg], 1);
    g_bucket[pos] = i;
}

// ---------------------------------------------------------------------------
// 5) gather-reduce: ONE warp per segment. Burst style: ALL index loads
//    issue first, then ALL (predicated) row loads, then the adds — no
//    accumulate sits between loads, so the whole gather is one MLP burst.
//    Lane l covers dims (2l, 2l+1) -> one LDG.64 per event per warp.
// ---------------------------------------------------------------------------
__global__ __launch_bounds__(256) void reduce_kernel(const float* __restrict__ in) {
    int seg  = (blockIdx.x * blockDim.x + threadIdx.x) >> 5;
    int lane = threadIdx.x & 31;
    if (seg >= NSEG) return;

    int cnt = __ldg(&g_cnt[seg]);
    float* dst = g_mean + (size_t)seg * DIN + lane * 2;
    if (cnt == 0) {               // warp-uniform early exit
        dst[0] = 0.f;
        dst[1] = 0.f;
        return;
    }
    int end   = __ldg(&g_cur[seg]);   // after scatter, cur == start + cnt
    int start = end - cnt;
    int last  = end - 1;

    // ---- burst 1: up to 16 clamped index loads (L2-resident bucket) ----
    int idx[16];
    #pragma unroll
    for (int t = 0; t < 16; t++) {
        int j = start + t;
        idx[t] = __ldg(&g_bucket[j < last ? j : last]);
    }

    // ---- burst 2: predicated row loads (disabled lanes fetch nothing) ----
    float2 v[16];
    #pragma unroll
    for (int t = 0; t < 16; t++) {
        v[t] = make_float2(0.f, 0.f);
        if (start + t < end)
            v[t] = *reinterpret_cast<const float2*>(
                in + (size_t)idx[t] * DIN + lane * 2);
    }

    // ---- adds (tree) ----
    float a0 = 0.f, a1 = 0.f;
    #pragma unroll
    for (int t = 0; t < 16; t += 4) {
        a0 += (v[t].x + v[t+1].x) + (v[t+2].x + v[t+3].x);
        a1 += (v[t].y + v[t+1].y) + (v[t+2].y + v[t+3].y);
    }

    // ---- rare tail (cnt > 16, ~3% of segments) ----
    for (int i = start + 16; i < end; i++) {
        int e = __ldg(&g_bucket[i]);
        float2 w = *reinterpret_cast<const float2*>(
            in + (size_t)e * DIN + lane * 2);
        a0 += w.x;
        a1 += w.y;
    }

    float inv = 1.f / (float)cnt;
    dst[0] = a0 * inv;
    dst[1] = a1 * inv;
}

// ---------------------------------------------------------------------------
// 6) per-batch fused  GEMM(means @ W) -> +bias(if nonempty) -> permute
// ---------------------------------------------------------------------------
__device__ __forceinline__ void unpack2(unsigned long long v, float& lo, float& hi) {
    asm("mov.b64 {%0, %1}, %2;" : "=f"(lo), "=f"(hi) : "l"(v));
}
__device__ __forceinline__ void fma2(unsigned long long& acc, float m,
                                     unsigned long long w) {
    unsigned long long mm;
    asm("mov.b64 %0, {%1, %1};" : "=l"(mm) : "f"(m));
    asm("fma.rn.f32x2 %0, %1, %2, %0;" : "+l"(acc) : "l"(mm), "l"(w));
}

__global__ __launch_bounds__(256) void pool_gemm_kernel(
    const float* __restrict__ Wm,     // [DIN][DOUT] row-major (k-major)
    const float* __restrict__ bias,   // [DOUT]
    float*       __restrict__ out)    // [BATCH][DOUT][WIN]
{
    __shared__ float s_mean[WIN * DIN];   // 3072 floats
    __shared__ float s_w[DIN * DOUT];     // 8192 floats; reused as out[128][49]
    __shared__ float s_b[DOUT];
    __shared__ float s_has[WIN];

    int b   = blockIdx.x;
    int tid = threadIdx.x;

    if (tid < WIN) s_has[tid] = (g_cnt[b * WIN + tid] > 0) ? 1.f : 0.f;
    if (tid < DOUT) s_b[tid] = bias[tid];

    // ---- load W (coalesced float4) ----
    {
        const float4* w4 = reinterpret_cast<const float4*>(Wm);
        float4* sw4 = reinterpret_cast<float4*>(s_w);
        #pragma unroll
        for (int i = tid; i < DIN * DOUT / 4; i += 256) sw4[i] = w4[i];
    }

    // ---- load means (already divided) ----
    {
        const float4* srow = reinterpret_cast<const float4*>(
            g_mean + (size_t)b * WIN * DIN);
        float4* sm4 = reinterpret_cast<float4*>(s_mean);
        #pragma unroll
        for (int i = tid; i < WIN * DIN / 4; i += 256) sm4[i] = srow[i];
    }
    __syncthreads();   // means + W ready

    // ---- compute 6w x 4d tile per thread ----
    int dg = tid & 31;
    int wg = tid >> 5;
    int d0 = dg * 2;

    unsigned long long acc0[6], acc1[6];
    #pragma unroll
    for (int i = 0; i < 6; i++) { acc0[i] = 0ull; acc1[i] = 0ull; }

    const float* mbase = s_mean + wg * 6 * DIN;

    #pragma unroll
    for (int kk = 0; kk < 16; kk++) {
        int k = kk * 4;
        float4 m[6];
        #pragma unroll
        for (int i = 0; i < 6; i++)
            m[i] = *reinterpret_cast<const float4*>(mbase + i * DIN + k);
        #pragma unroll
        for (int j = 0; j < 4; j++) {
            unsigned long long w0 = *reinterpret_cast<const unsigned long long*>(
                s_w + (k + j) * DOUT + d0);
            unsigned long long w1 = *reinterpret_cast<const unsigned long long*>(
                s_w + (k + j) * DOUT + 64 + d0);
            #pragma unroll
            for (int i = 0; i < 6; i++) {
                float mv = (j == 0) ? m[i].x : (j == 1) ? m[i].y
                         : (j == 2) ? m[i].z : m[i].w;
                fma2(acc0[i], mv, w0);
                fma2(acc1[i], mv, w1);
            }
        }
    }

    __syncthreads();   // everyone done reading s_w; reuse as out staging

    // ---- stage results as out[d][w] pad-49 (+bias if nonempty) ----
    float b0x = s_b[d0],      b0y = s_b[d0 + 1];
    float b1x = s_b[d0 + 64], b1y = s_b[d0 + 65];
    #pragma unroll
    for (int i = 0; i < 6; i++) {
        int w = wg * 6 + i;
        float has = s_has[w];
        float a0x, a0y, a1x, a1y;
        unpack2(acc0[i], a0x, a0y);
        unpack2(acc1[i], a1x, a1y);
        s_w[(d0    ) * 49 + w] = a0x + has * b0x;
        s_w[(d0 + 1) * 49 + w] = a0y + has * b0y;
        s_w[(d0 + 64) * 49 + w] = a1x + has * b1x;
        s_w[(d0 + 65) * 49 + w] = a1y + has * b1y;
    }
    __syncthreads();

    // ---- coalesced float4 store of out[b][d][w] ----
    float* obase = out + (size_t)b * DOUT * WIN;
    #pragma unroll
    for (int it = 0; it < 6; it++) {
        int j = it * 1024 + tid * 4;   // 48 % 4 == 0 -> all 4 elems share d
        int d = j / 48;
        int w = j - d * 48;
        const float* src = s_w + d * 49 + w;
        float4 v = make_float4(src[0], src[1], src[2], src[3]);
        *reinterpret_cast<float4*>(obase + j) = v;
    }
}

// ---------------------------------------------------------------------------
extern "C" void kernel_launch(void* const* d_in, const int* in_sizes, int n_in,
                              void* d_out, int out_size) {
    const float* input = (const float*)d_in[0];
    const float* Wm    = (const float*)d_in[1];
    const float* bias  = (const float*)d_in[2];

    const int* bi;
    const int* wi;
    int n_events;
    if (n_in >= 6 && in_sizes[3] == 1) {
        bi = (const int*)d_in[4];
        wi = (const int*)d_in[5];
        n_events = in_sizes[4];
    } else {
        bi = (const int*)d_in[3];
        wi = (const int*)d_in[4];
        n_events = in_sizes[3];
    }

    int eb = (n_events + 255) / 256;

    zero_cnt_kernel<<<(NSEG + 255) / 256, 256>>>();
    hist_kernel<<<eb, 256>>>(bi, wi, n_events);
    scan_a_kernel<<<SCAN_NBLK, 1024>>>();
    scan_c_kernel<<<NSEG / 256, 256>>>();
    scatter_idx_kernel<<<eb, 256>>>(bi, wi, n_events);
    reduce_kernel<<<NSEG / 8, 256>>>(input);
    pool_gemm_kernel<<<BATCH, 256>>>(Wm, bias, (float*)d_out);
}

// round 10
// speedup vs baseline: 1.0456x; 1.0456x over previous
#include <cuda_runtime.h>

// Problem constants (fixed-shape problem)
#define WIN   48
#define DIN   64
#define DOUT  128
#define BATCH 4096
#define NSEG  (BATCH * WIN)      // 196608 segments
#define CAP   64                 // bucket slots per segment (P(cnt>64) ~ 1e-30)

// Scratch
__device__ int   g_cur[NSEG];            // per-segment cursor (== count after scatter)
__device__ int   g_bucket[NSEG * CAP];   // event ids, fixed-stride buckets (50 MB)
__device__ float g_mean[NSEG * DIN];     // segment means

// ---------------------------------------------------------------------------
// 1) zero cursors
// ---------------------------------------------------------------------------
__global__ void zero_cur_kernel() {
    int i = blockIdx.x * blockDim.x + threadIdx.x;
    if (i < NSEG) g_cur[i] = 0;
}

// ---------------------------------------------------------------------------
// 2) scatter event indices into fixed-capacity buckets (bump allocation).
//    No histogram, no scan.
// ---------------------------------------------------------------------------
__global__ void scatter_idx_kernel(const int* __restrict__ bi,
                                   const int* __restrict__ wi, int n) {
    int i = blockIdx.x * blockDim.x + threadIdx.x;
    if (i >= n) return;
    int seg = bi[i] * WIN + wi[i];
    int pos = atomicAdd(&g_cur[seg], 1);
    if (pos < CAP) g_bucket[(seg << 6) + pos] = i;   // clamp for safety
}

// ---------------------------------------------------------------------------
// 3) gather-reduce: ONE warp per segment, burst loads (all idx, then all
//    predicated rows, then adds). Lane l covers dims (2l, 2l+1) -> LDG.64.
//    cnt comes straight from the cursor; empty segments write zeros.
// ---------------------------------------------------------------------------
__global__ __launch_bounds__(256) void reduce_kernel(const float* __restrict__ in) {
    int seg  = (blockIdx.x * blockDim.x + threadIdx.x) >> 5;
    int lane = threadIdx.x & 31;
    if (seg >= NSEG) return;

    int cnt = __ldg(&g_cur[seg]);
    if (cnt > CAP) cnt = CAP;
    float* dst = g_mean + (size_t)seg * DIN + lane * 2;
    if (cnt == 0) {               // warp-uniform early exit
        dst[0] = 0.f;
        dst[1] = 0.f;
        return;
    }
    int base = seg << 6;          // seg * CAP
    int last = cnt - 1;

    // ---- burst 1: up to 16 clamped index loads (contiguous, L2-friendly) ----
    int idx[16];
    #pragma unroll
    for (int t = 0; t < 16; t++)
        idx[t] = __ldg(&g_bucket[base + (t < last ? t : last)]);

    // ---- burst 2: predicated row loads ----
    float2 v[16];
    #pragma unroll
    for (int t = 0; t < 16; t++) {
        v[t] = make_float2(0.f, 0.f);
        if (t < cnt)
            v[t] = *reinterpret_cast<const float2*>(
                in + (size_t)idx[t] * DIN + lane * 2);
    }

    // ---- adds (tree) ----
    float a0 = 0.f, a1 = 0.f;
    #pragma unroll
    for (int t = 0; t < 16; t += 4) {
        a0 += (v[t].x + v[t+1].x) + (v[t+2].x + v[t+3].x);
        a1 += (v[t].y + v[t+1].y) + (v[t+2].y + v[t+3].y);
    }

    // ---- rare tail (cnt > 16, ~3% of segments) ----
    for (int t = 16; t < cnt; t++) {
        int e = __ldg(&g_bucket[base + t]);
        float2 w = *reinterpret_cast<const float2*>(
            in + (size_t)e * DIN + lane * 2);
        a0 += w.x;
        a1 += w.y;
    }

    float inv = 1.f / (float)cnt;
    dst[0] = a0 * inv;
    dst[1] = a1 * inv;
}

// ---------------------------------------------------------------------------
// 4) per-batch fused  GEMM(means @ W) -> +bias(if nonempty) -> permute
// ---------------------------------------------------------------------------
__device__ __forceinline__ void unpack2(unsigned long long v, float& lo, float& hi) {
    asm("mov.b64 {%0, %1}, %2;" : "=f"(lo), "=f"(hi) : "l"(v));
}
__device__ __forceinline__ void fma2(unsigned long long& acc, float m,
                                     unsigned long long w) {
    unsigned long long mm;
    asm("mov.b64 %0, {%1, %1};" : "=l"(mm) : "f"(m));
    asm("fma.rn.f32x2 %0, %1, %2, %0;" : "+l"(acc) : "l"(mm), "l"(w));
}

__global__ __launch_bounds__(256) void pool_gemm_kernel(
    const float* __restrict__ Wm,     // [DIN][DOUT] row-major (k-major)
    const float* __restrict__ bias,   // [DOUT]
    float*       __restrict__ out)    // [BATCH][DOUT][WIN]
{
    __shared__ float s_mean[WIN * DIN];   // 3072 floats
    __shared__ float s_w[DIN * DOUT];     // 8192 floats; reused as out[128][49]
    __shared__ float s_b[DOUT];
    __shared__ float s_has[WIN];

    int b   = blockIdx.x;
    int tid = threadIdx.x;

    if (tid < WIN) s_has[tid] = (g_cur[b * WIN + tid] > 0) ? 1.f : 0.f;
    if (tid < DOUT) s_b[tid] = bias[tid];

    // ---- load W (coalesced float4) ----
    {
        const float4* w4 = reinterpret_cast<const float4*>(Wm);
        float4* sw4 = reinterpret_cast<float4*>(s_w);
        #pragma unroll
        for (int i = tid; i < DIN * DOUT / 4; i += 256) sw4[i] = w4[i];
    }

    // ---- load means (already divided) ----
    {
        const float4* srow = reinterpret_cast<const float4*>(
            g_mean + (size_t)b * WIN * DIN);
        float4* sm4 = reinterpret_cast<float4*>(s_mean);
        #pragma unroll
        for (int i = tid; i < WIN * DIN / 4; i += 256) sm4[i] = srow[i];
    }
    __syncthreads();   // means + W ready

    // ---- compute 6w x 4d tile per thread ----
    int dg = tid & 31;
    int wg = tid >> 5;
    int d0 = dg * 2;

    unsigned long long acc0[6], acc1[6];
    #pragma unroll
    for (int i = 0; i < 6; i++) { acc0[i] = 0ull; acc1[i] = 0ull; }

    const float* mbase = s_mean + wg * 6 * DIN;

    #pragma unroll
    for (int kk = 0; kk < 16; kk++) {
        int k = kk * 4;
        float4 m[6];
        #pragma unroll
        for (int i = 0; i < 6; i++)
            m[i] = *reinterpret_cast<const float4*>(mbase + i * DIN + k);
        #pragma unroll
        for (int j = 0; j < 4; j++) {
            unsigned long long w0 = *reinterpret_cast<const unsigned long long*>(
                s_w + (k + j) * DOUT + d0);
            unsigned long long w1 = *reinterpret_cast<const unsigned long long*>(
                s_w + (k + j) * DOUT + 64 + d0);
            #pragma unroll
            for (int i = 0; i < 6; i++) {
                float mv = (j == 0) ? m[i].x : (j == 1) ? m[i].y
                         : (j == 2) ? m[i].z : m[i].w;
                fma2(acc0[i], mv, w0);
                fma2(acc1[i], mv, w1);
            }
        }
    }

    __syncthreads();   // everyone done reading s_w; reuse as out staging

    // ---- stage results as out[d][w] pad-49 (+bias if nonempty) ----
    float b0x = s_b[d0],      b0y = s_b[d0 + 1];
    float b1x = s_b[d0 + 64], b1y = s_b[d0 + 65];
    #pragma unroll
    for (int i = 0; i < 6; i++) {
        int w = wg * 6 + i;
        float has = s_has[w];
        float a0x, a0y, a1x, a1y;
        unpack2(acc0[i], a0x, a0y);
        unpack2(acc1[i], a1x, a1y);
        s_w[(d0    ) * 49 + w] = a0x + has * b0x;
        s_w[(d0 + 1) * 49 + w] = a0y + has * b0y;
        s_w[(d0 + 64) * 49 + w] = a1x + has * b1x;
        s_w[(d0 + 65) * 49 + w] = a1y + has * b1y;
    }
    __syncthreads();

    // ---- coalesced float4 store of out[b][d][w] ----
    float* obase = out + (size_t)b * DOUT * WIN;
    #pragma unroll
    for (int it = 0; it < 6; it++) {
        int j = it * 1024 + tid * 4;   // 48 % 4 == 0 -> all 4 elems share d
        int d = j / 48;
        int w = j - d * 48;
        const float* src = s_w + d * 49 + w;
        float4 v = make_float4(src[0], src[1], src[2], src[3]);
        *reinterpret_cast<float4*>(obase + j) = v;
    }
}

// ---------------------------------------------------------------------------
extern "C" void kernel_launch(void* const* d_in, const int* in_sizes, int n_in,
                              void* d_out, int out_size) {
    const float* input = (const float*)d_in[0];
    const float* Wm    = (const float*)d_in[1];
    const float* bias  = (const float*)d_in[2];

    const int* bi;
    const int* wi;
    int n_events;
    if (n_in >= 6 && in_sizes[3] == 1) {
        bi = (const int*)d_in[4];
        wi = (const int*)d_in[5];
        n_events = in_sizes[4];
    } else {
        bi = (const int*)d_in[3];
        wi = (const int*)d_in[4];
        n_events = in_sizes[3];
    }

    int eb = (n_events + 255) / 256;

    zero_cur_kernel<<<(NSEG + 255) / 256, 256>>>();
    scatter_idx_kernel<<<eb, 256>>>(bi, wi, n_events);
    reduce_kernel<<<NSEG / 8, 256>>>(input);
    pool_gemm_kernel<<<BATCH, 256>>>(Wm, bias, (float*)d_out);
}

// round 11
// speedup vs baseline: 1.0769x; 1.0300x over previous
#include <cuda_runtime.h>
#include <cstdint>

// Problem constants (fixed-shape problem)
#define WIN   48
#define DIN   64
#define DOUT  128
#define BATCH 4096
#define NSEG  (BATCH * WIN)      // 196608 segments
#define CAP   64                 // bucket slots per segment (P(cnt>64) ~ 1e-30)

#define A_PAD 68                 // means row stride (floats): banks 4g+c bijective
#define W_PAD 136                // W row stride (floats): banks 8c+g bijective

// Scratch
__device__ int   g_cur[NSEG];            // per-segment cursor (== count after scatter)
__device__ int   g_bucket[NSEG * CAP];   // event ids, fixed-stride buckets (50 MB)
__device__ float g_mean[NSEG * DIN];     // segment means

// ---------------------------------------------------------------------------
// 1) zero cursors
// ---------------------------------------------------------------------------
__global__ void zero_cur_kernel() {
    int i = blockIdx.x * blockDim.x + threadIdx.x;
    if (i < NSEG) g_cur[i] = 0;
}

// ---------------------------------------------------------------------------
// 2) scatter event indices into fixed-capacity buckets (bump allocation)
// ---------------------------------------------------------------------------
__global__ void scatter_idx_kernel(const int* __restrict__ bi,
                                   const int* __restrict__ wi, int n) {
    int i = blockIdx.x * blockDim.x + threadIdx.x;
    if (i >= n) return;
    int seg = bi[i] * WIN + wi[i];
    int pos = atomicAdd(&g_cur[seg], 1);
    if (pos < CAP) g_bucket[(seg << 6) + pos] = i;   // clamp for safety
}

// ---------------------------------------------------------------------------
// 3) gather-reduce: ONE warp per segment, burst loads. Lane l covers dims
//    (2l, 2l+1) -> one LDG.64 per event. Empty segments write zeros.
// ---------------------------------------------------------------------------
__global__ __launch_bounds__(256) void reduce_kernel(const float* __restrict__ in) {
    int seg  = (blockIdx.x * blockDim.x + threadIdx.x) >> 5;
    int lane = threadIdx.x & 31;
    if (seg >= NSEG) return;

    int cnt = __ldg(&g_cur[seg]);
    if (cnt > CAP) cnt = CAP;
    float* dst = g_mean + (size_t)seg * DIN + lane * 2;
    if (cnt == 0) {               // warp-uniform early exit
        dst[0] = 0.f;
        dst[1] = 0.f;
        return;
    }
    int base = seg << 6;          // seg * CAP
    int last = cnt - 1;

    int idx[16];
    #pragma unroll
    for (int t = 0; t < 16; t++)
        idx[t] = __ldg(&g_bucket[base + (t < last ? t : last)]);

    float2 v[16];
    #pragma unroll
    for (int t = 0; t < 16; t++) {
        v[t] = make_float2(0.f, 0.f);
        if (t < cnt)
            v[t] = *reinterpret_cast<const float2*>(
                in + (size_t)idx[t] * DIN + lane * 2);
    }

    float a0 = 0.f, a1 = 0.f;
    #pragma unroll
    for (int t = 0; t < 16; t += 4) {
        a0 += (v[t].x + v[t+1].x) + (v[t+2].x + v[t+3].x);
        a1 += (v[t].y + v[t+1].y) + (v[t+2].y + v[t+3].y);
    }

    for (int t = 16; t < cnt; t++) {
        int e = __ldg(&g_bucket[base + t]);
        float2 w = *reinterpret_cast<const float2*>(
            in + (size_t)e * DIN + lane * 2);
        a0 += w.x;
        a1 += w.y;
    }

    float inv = 1.f / (float)cnt;
    dst[0] = a0 * inv;
    dst[1] = a1 * inv;
}

// ---------------------------------------------------------------------------
// 4) per-batch GEMM on tensor cores: (means @ W) with 3xTF32 precision
//    -> +bias(if nonempty) -> permute to out[b][d][w]
//    M=48 (3 m16 tiles), N=128 (16 n8 tiles), K=64 (8 k8 steps).
//    Warp w handles all 3 m-tiles x n-tiles {2w, 2w+1}.
// ---------------------------------------------------------------------------
__device__ __forceinline__ uint32_t tf32_bits(float x) {
    uint32_t u;
    asm("cvt.rna.tf32.f32 %0, %1;" : "=r"(u) : "f"(x));
    return u;
}
__device__ __forceinline__ void mma_tf32(float* c, const uint32_t* a,
                                         const uint32_t* b) {
    asm("mma.sync.aligned.m16n8k8.row.col.f32.tf32.tf32.f32 "
        "{%0,%1,%2,%3}, {%4,%5,%6,%7}, {%8,%9}, {%0,%1,%2,%3};"
        : "+f"(c[0]), "+f"(c[1]), "+f"(c[2]), "+f"(c[3])
        : "r"(a[0]), "r"(a[1]), "r"(a[2]), "r"(a[3]), "r"(b[0]), "r"(b[1]));
}

__global__ __launch_bounds__(256) void pool_gemm_kernel(
    const float* __restrict__ Wm,     // [DIN][DOUT] row-major (k-major)
    const float* __restrict__ bias,   // [DOUT]
    float*       __restrict__ out)    // [BATCH][DOUT][WIN]
{
    __shared__ float s_a[WIN * A_PAD];    // means, padded rows   (13056 B)
    __shared__ float s_w[DIN * W_PAD];    // W, padded rows       (34816 B); reused as out[128][49]
    __shared__ float s_b[DOUT];
    __shared__ float s_has[WIN];

    int b   = blockIdx.x;
    int tid = threadIdx.x;
    int lane = tid & 31;
    int wg   = tid >> 5;
    int g    = lane >> 2;     // group id 0..7
    int tig  = lane & 3;      // thread in group 0..3

    if (tid < WIN) s_has[tid] = (g_cur[b * WIN + tid] > 0) ? 1.f : 0.f;
    if (tid < DOUT) s_b[tid] = bias[tid];

    // ---- load W into padded smem (row stride 136; 544B row, 16B aligned) ----
    {
        const float4* w4 = reinterpret_cast<const float4*>(Wm);
        #pragma unroll
        for (int i = tid; i < DIN * DOUT / 4; i += 256) {
            int row = i >> 5;          // /32 float4 per row
            int c4  = i & 31;
            *reinterpret_cast<float4*>(s_w + row * W_PAD + c4 * 4) = w4[i];
        }
    }
    // ---- load means into padded smem (row stride 68; 272B row, 16B aligned) ----
    {
        const float4* m4 = reinterpret_cast<const float4*>(
            g_mean + (size_t)b * WIN * DIN);
        #pragma unroll
        for (int i = tid; i < WIN * DIN / 4; i += 256) {
            int row = i >> 4;          // /16 float4 per row
            int c4  = i & 15;
            *reinterpret_cast<float4*>(s_a + row * A_PAD + c4 * 4) = m4[i];
        }
    }
    __syncthreads();

    // ---- accumulators: 3 m-tiles x 2 n-tiles x 4 ----
    float acc[3][2][4];
    #pragma unroll
    for (int mt = 0; mt < 3; mt++)
        #pragma unroll
        for (int nt = 0; nt < 2; nt++)
            #pragma unroll
            for (int q = 0; q < 4; q++) acc[mt][nt][q] = 0.f;

    int n0 = wg * 16;   // this warp's 16 output columns (2 n8 tiles)

    #pragma unroll
    for (int ks = 0; ks < 8; ks++) {
        int k0 = ks * 8;

        // ---- A fragments (fp32) + tf32 hi/lo split ----
        uint32_t ahi[3][4], alo[3][4];
        #pragma unroll
        for (int mt = 0; mt < 3; mt++) {
            const float* ab = s_a + (mt * 16 + g) * A_PAD + k0 + tig;
            float a0 = ab[0];
            float a1 = ab[8 * A_PAD];
            float a2 = ab[4];
            float a3 = ab[8 * A_PAD + 4];
            ahi[mt][0] = tf32_bits(a0);
            ahi[mt][1] = tf32_bits(a1);
            ahi[mt][2] = tf32_bits(a2);
            ahi[mt][3] = tf32_bits(a3);
            alo[mt][0] = tf32_bits(a0 - __uint_as_float(ahi[mt][0]));
            alo[mt][1] = tf32_bits(a1 - __uint_as_float(ahi[mt][1]));
            alo[mt][2] = tf32_bits(a2 - __uint_as_float(ahi[mt][2]));
            alo[mt][3] = tf32_bits(a3 - __uint_as_float(ahi[mt][3]));
        }

        // ---- B fragments (fp32) + tf32 hi/lo split ----
        uint32_t bhi[2][2], blo[2][2];
        #pragma unroll
        for (int nt = 0; nt < 2; nt++) {
            const float* bb = s_w + (k0 + tig) * W_PAD + n0 + nt * 8 + g;
            float b0 = bb[0];
            float b1 = bb[4 * W_PAD];
            bhi[nt][0] = tf32_bits(b0);
            bhi[nt][1] = tf32_bits(b1);
            blo[nt][0] = tf32_bits(b0 - __uint_as_float(bhi[nt][0]));
            blo[nt][1] = tf32_bits(b1 - __uint_as_float(bhi[nt][1]));
        }

        // ---- 3xTF32 mma: hi*hi + hi*lo + lo*hi ----
        #pragma unroll
        for (int mt = 0; mt < 3; mt++)
            #pragma unroll
            for (int nt = 0; nt < 2; nt++) {
                mma_tf32(acc[mt][nt], ahi[mt], bhi[nt]);
                mma_tf32(acc[mt][nt], ahi[mt], blo[nt]);
                mma_tf32(acc[mt][nt], alo[mt], bhi[nt]);
            }
    }

    __syncthreads();   // all warps done reading s_w; reuse as out staging

    // ---- stage results as out[d][w] pad-49 (+bias if nonempty) ----
    // C layout: c0:(g, 2*tig) c1:(g, 2*tig+1) c2:(g+8, 2*tig) c3:(g+8, 2*tig+1)
    #pragma unroll
    for (int mt = 0; mt < 3; mt++) {
        int w0 = mt * 16 + g;
        int w1 = w0 + 8;
        float h0 = s_has[w0];
        float h1 = s_has[w1];
        #pragma unroll
        for (int nt = 0; nt < 2; nt++) {
            int d = n0 + nt * 8 + tig * 2;
            float bx = s_b[d], by = s_b[d + 1];
            s_w[(d    ) * 49 + w0] = acc[mt][nt][0] + h0 * bx;
            s_w[(d + 1) * 49 + w0] = acc[mt][nt][1] + h0 * by;
            s_w[(d    ) * 49 + w1] = acc[mt][nt][2] + h1 * bx;
            s_w[(d + 1) * 49 + w1] = acc[mt][nt][3] + h1 * by;
        }
    }
    __syncthreads();

    // ---- coalesced float4 store of out[b][d][w] ----
    float* obase = out + (size_t)b * DOUT * WIN;
    #pragma unroll
    for (int it = 0; it < 6; it++) {
        int j = it * 1024 + tid * 4;   // 48 % 4 == 0 -> all 4 elems share d
        int d = j / 48;
        int w = j - d * 48;
        const float* src = s_w + d * 49 + w;
        float4 v = make_float4(src[0], src[1], src[2], src[3]);
        *reinterpret_cast<float4*>(obase + j) = v;
    }
}

// ---------------------------------------------------------------------------
extern "C" void kernel_launch(void* const* d_in, const int* in_sizes, int n_in,
                              void* d_out, int out_size) {
    const float* input = (const float*)d_in[0];
    const float* Wm    = (const float*)d_in[1];
    const float* bias  = (const float*)d_in[2];

    const int* bi;
    const int* wi;
    int n_events;
    if (n_in >= 6 && in_sizes[3] == 1) {
        bi = (const int*)d_in[4];
        wi = (const int*)d_in[5];
        n_events = in_sizes[4];
    } else {
        bi = (const int*)d_in[3];
        wi = (const int*)d_in[4];
        n_events = in_sizes[3];
    }

    int eb = (n_events + 255) / 256;

    zero_cur_kernel<<<(NSEG + 255) / 256, 256>>>();
    scatter_idx_kernel<<<eb, 256>>>(bi, wi, n_events);
    reduce_kernel<<<NSEG / 8, 256>>>(input);
    pool_gemm_kernel<<<BATCH, 256>>>(Wm, bias, (float*)d_out);
}